// round 17
// baseline (speedup 1.0000x reference)
#include <cuda_runtime.h>
#include <cuda_bf16.h>
#include <math.h>

#define NNODE 4095
#define HID   768
#define GC    2304
#define KTOT  1536
#define NWAVE 34
#define MAXW  1280
#define GRID  148
#define PTHR  256

// leaf-kernel tile params (fp32 engine unchanged)
#define LTHR  256
#define LBM   64
#define LBK   16
#define LBNG  64
#define LBN   192
#define LAP   (LBM+4)

// ---------------- mma.sync helper (sm_80-class HMMA, valid on base sm_103) ----
__device__ __forceinline__ void mma_bf16(float* d, const unsigned* a,
                                         unsigned b0, unsigned b1) {
    asm volatile(
        "mma.sync.aligned.m16n8k16.row.col.f32.bf16.bf16.f32 "
        "{%0,%1,%2,%3}, {%4,%5,%6,%7}, {%8,%9}, {%0,%1,%2,%3};"
        : "+f"(d[0]), "+f"(d[1]), "+f"(d[2]), "+f"(d[3])
        : "r"(a[0]), "r"(a[1]), "r"(a[2]), "r"(a[3]), "r"(b0), "r"(b1));
}

// ---------------- device scratch ----------------
__device__ float d_H[NNODE*HID];
__device__ float d_C[NNODE*HID];
__device__ float d_LC[NNODE*HID];
__device__ __nv_bfloat16 d_Hh[NNODE*HID];
__device__ __nv_bfloat16 d_Hl[NNODE*HID];
__device__ __nv_bfloat16 d_LHh[NNODE*HID];
__device__ __nv_bfloat16 d_LHl[NNODE*HID];
// B weights packed in mma fragment order: [jt(18)][kc(96)][nf(16)][lane(32)][reg(2)] bf16x2
__device__ __nv_bfloat16 d_Bfh[(size_t)GC*KTOT];
__device__ __nv_bfloat16 d_Bfl[(size_t)GC*KTOT];
__device__ float d_bsc[GC];
__device__ float d_G[(size_t)MAXW*GC];
__device__ int   d_listB[NWAVE*MAXW];
__device__ int   d_listC[NWAVE*MAXW];
__device__ int   d_nb[NWAVE];
__device__ int   d_nc[NWAVE];
__device__ int   d_deps[NNODE];
__device__ int   d_nextsib[NNODE];
__device__ int   d_parlast[NNODE];
__device__ int   d_leafarr[NNODE];
__device__ int   d_nleaf;
__device__ unsigned g_cnt;
__device__ volatile unsigned g_gen;

// ---------------- grid barrier ----------------
__device__ __forceinline__ void gbar() {
    __syncthreads();
    if (threadIdx.x == 0) {
        unsigned g = g_gen;
        __threadfence();
        if (atomicAdd(&g_cnt, 1u) == GRID - 1) {
            g_cnt = 0;
            __threadfence();
            g_gen = g + 1;
        } else {
            while (g_gen == g) { __nanosleep(32); }
        }
        __threadfence();
    }
    __syncthreads();
}

// ---------------- prep ----------------
__global__ void prep1(const float* __restrict__ Ws, const float* __restrict__ Wc,
                      const float* __restrict__ bs, const float* __restrict__ bc) {
    long i0 = (long)blockIdx.x * blockDim.x + threadIdx.x;
    long stride = (long)gridDim.x * blockDim.x;
    for (long t = i0; t < (long)GC * KTOT; t += stride) {
        int j = (int)(t / KTOT), k = (int)(t % KTOT);
        float v = (k < HID) ? Ws[(size_t)j*HID + k] : Wc[(size_t)j*HID + (k - HID)];
        __nv_bfloat16 hi = __float2bfloat16(v);
        __nv_bfloat16 lo = __float2bfloat16(v - __bfloat162float(hi));
        int jt = j >> 7, nl = j & 127, nf = nl >> 3, ng = nl & 7;
        int kc = k >> 4, lane = ng*4 + ((k & 7) >> 1), reg = (k & 15) >> 3, half = k & 1;
        size_t idx = (((((size_t)jt*96 + kc)*16 + nf)*32 + lane)*2 + reg)*2 + half;
        d_Bfh[idx] = hi;
        d_Bfl[idx] = lo;
    }
    for (long t = i0; t < GC; t += stride) d_bsc[t] = bs[t] + bc[t];
    for (long t = i0; t < NNODE; t += stride) { d_nextsib[t] = -1; d_parlast[t] = -1; }
    for (long t = i0; t < NWAVE; t += stride) { d_nb[t] = 0; d_nc[t] = 0; }
    if (i0 == 0) { d_nleaf = 0; g_cnt = 0; g_gen = 0; }
}

__global__ void prep2(const int* __restrict__ leaf_mask,
                      const int* __restrict__ child_idx,
                      const int* __restrict__ prev_idx) {
    int i = blockIdx.x * blockDim.x + threadIdx.x;
    if (i >= NNODE) return;
    int pi = prev_idx[i];
    int isleaf = leaf_mask[i];
    d_deps[i] = (pi >= 0 ? 1 : 0) + (isleaf ? 0 : 1);
    if (pi >= 0) d_nextsib[pi] = i;
    if (!isleaf) d_parlast[child_idx[i]] = i;
    if (isleaf) { int s = atomicAdd(&d_nleaf, 1); if (s < NNODE) d_leafarr[s] = i; }
    if (pi < 0 && isleaf) { int s = atomicAdd(&d_nc[0], 1); if (s < MAXW) d_listC[s] = i; }
}

__global__ void copyout_kernel(float* __restrict__ out, int out_size) {
    int j = blockIdx.x * blockDim.x + threadIdx.x;
    if (j < HID && j < out_size) out[j] = d_H[(size_t)(NNODE - 1) * HID + j];
}

// ---------------- leaf GEMM + gates (fp32 engine; adds bf16 split stores) ----
__global__ __launch_bounds__(LTHR)
void leaf_kernel(const int* __restrict__ word,
                 const float* __restrict__ emb,
                 const float* __restrict__ Wx,
                 const float* __restrict__ bx,
                 const float* __restrict__ bh)
{
    __shared__ float smem[LBK*LAP + LBK*LBN];
    float* As = smem;
    float* Bs = smem + LBK*LAP;
    __shared__ const float* s_x[LBM];
    __shared__ int s_node[LBM];

    int nl = d_nleaf;
    int base = blockIdx.x * LBM;
    if (base >= nl) return;
    int rows = min(LBM, nl - base);
    int tid = threadIdx.x;
    int jt = blockIdx.y;

    if (tid < LBM) {
        if (tid < rows) {
            int node = d_leafarr[base + tid];
            s_node[tid] = node;
            s_x[tid] = emb + (size_t)word[node] * 300;
        } else { s_node[tid] = -1; s_x[tid] = 0; }
    }
    __syncthreads();

    float acc[8][6];
    #pragma unroll
    for (int r = 0; r < 8; r++)
        #pragma unroll
        for (int c = 0; c < 6; c++) acc[r][c] = 0.f;

    int tmg = tid >> 5;
    int tng = tid & 31;
    int lm  = tid >> 2;
    int lk  = (tid & 3) * 4;

    for (int k0 = 0; k0 < 300; k0 += LBK) {
        {
            const float* rp = s_x[lm];
            #pragma unroll
            for (int j = 0; j < 4; j++) {
                int k = k0 + lk + j;
                As[(lk+j)*LAP + lm] = (rp && k < 300) ? rp[k] : 0.f;
            }
        }
        #pragma unroll
        for (int pass = 0; pass < 3; pass++) {
            int n = pass*64 + lm;
            int g = n >> 6, col = n & 63;
            int jp = (g == 0 ? 0 : (g == 1 ? HID : 3*HID)) + jt*LBNG + col;
            #pragma unroll
            for (int j = 0; j < 4; j++) {
                int k = k0 + lk + j;
                Bs[(lk+j)*LBN + n] = (k < 300) ? Wx[(size_t)jp*300 + k] : 0.f;
            }
        }
        __syncthreads();
        #pragma unroll
        for (int k = 0; k < LBK; k++) {
            float a[8], b[6];
            float4 a0 = *reinterpret_cast<const float4*>(&As[k*LAP + tmg*8]);
            float4 a1 = *reinterpret_cast<const float4*>(&As[k*LAP + tmg*8 + 4]);
            a[0]=a0.x; a[1]=a0.y; a[2]=a0.z; a[3]=a0.w;
            a[4]=a1.x; a[5]=a1.y; a[6]=a1.z; a[7]=a1.w;
            #pragma unroll
            for (int c = 0; c < 6; c++) b[c] = Bs[k*LBN + tng*6 + c];
            #pragma unroll
            for (int r = 0; r < 8; r++)
                #pragma unroll
                for (int c = 0; c < 6; c++)
                    acc[r][c] += a[r]*b[c];
        }
        __syncthreads();
    }

    float* Gs = smem;
    for (int s = 0; s < 4; s++) {
        if ((tmg >> 1) == s) {
            int rl = (tmg & 1) * 8;
            #pragma unroll
            for (int r = 0; r < 8; r++)
                #pragma unroll
                for (int c = 0; c < 6; c++)
                    Gs[(rl+r)*LBN + tng*6 + c] = acc[r][c];
        }
        __syncthreads();
        for (int it = tid; it < 16*LBNG; it += LTHR) {
            int r = it >> 6, j = it & 63, m = s*16 + r;
            if (m < rows) {
                int jg = jt*LBNG + j;
                float gi = Gs[r*LBN + j]       + bx[jg]        + bh[jg];
                float go = Gs[r*LBN + 64 + j]  + bx[HID+jg]    + bh[HID+jg];
                float gc = Gs[r*LBN + 128 + j] + bx[3*HID+jg]  + bh[3*HID+jg];
                float si = 1.f/(1.f + expf(-gi));
                float so = 1.f/(1.f + expf(-go));
                float cell = si * tanhf(gc);
                float hidv = so * tanhf(cell);
                int node = s_node[m];
                size_t idx = (size_t)node*HID + jg;
                d_LC[idx] = cell;
                __nv_bfloat16 hh = __float2bfloat16(hidv);
                d_LHh[idx] = hh;
                d_LHl[idx] = __float2bfloat16(hidv - __bfloat162float(hh));
            }
        }
        __syncthreads();
    }
}

// ---------------- persistent wave kernel: HMMA split-bf16 ----------------
// dynamic smem: [0,4096): 4 pointer tables (128 x 8B each); [4096, 4096+65536): A frags
// A frag u32 index: ((((kc*8 + mc)*2 + side)*4 + reg)*32 + lane)
#define SM_AOFF 4096
#define SMEM_P  (SM_AOFF + 65536)

__global__ __launch_bounds__(PTHR, 1)
void persist_kernel(const int* __restrict__ leaf_mask,
                    const int* __restrict__ child_idx,
                    const int* __restrict__ prev_idx)
{
    extern __shared__ char smem[];
    const __nv_bfloat16** s_hx_h = (const __nv_bfloat16**)(smem);
    const __nv_bfloat16** s_hx_l = s_hx_h + 128;
    const __nv_bfloat16** s_hc_h = s_hx_l + 128;
    const __nv_bfloat16** s_hc_l = s_hc_h + 128;
    unsigned* A32 = (unsigned*)(smem + SM_AOFF);

    int tid = threadIdx.x, bid = blockIdx.x;
    int lane = tid & 31, wid = tid >> 5;

    for (int w = 0; w < NWAVE - 1; w++) {
        gbar();
        int nb = min(d_nb[w], MAXW), nc = min(d_nc[w], MAXW);
        int rows = nb + nc;
        if (rows == 0) break;

        int rtB = (nb + 127) >> 7, rtC = (nc + 127) >> 7;
        int ntiles = (rtB + rtC) * 18;

        for (int t = bid; t < ntiles; t += GRID) {
            int jt = t % 18, rt = t / 18;
            const int* list; int base, cnt, r0, chbeg;
            if (rt < rtB) { list = d_listB + w*MAXW; base = rt << 7;        cnt = nb; r0 = base;      chbeg = 0; }
            else          { list = d_listC + w*MAXW; base = (rt - rtB) << 7; cnt = nc; r0 = nb + base; chbeg = 6; }
            int rows_t = min(128, cnt - base);

            int mchunks = rows_t > 64 ? 8 : rows_t > 32 ? 4 : rows_t > 16 ? 2 : 1;
            int mlog = rows_t > 64 ? 3 : rows_t > 32 ? 2 : rows_t > 16 ? 1 : 0;
            int mrows = mchunks << 4;
            int mc = wid & (mchunks - 1);
            int ngrp = wid >> mlog;
            int nf_cnt = mchunks << 1;
            int nf0 = ngrp * nf_cnt;

            __syncthreads();
            if (tid < 128) {
                if (tid < rows_t) {
                    int node = list[base + tid];
                    int pi = prev_idx[node];
                    size_t po = (size_t)pi * HID;
                    s_hx_h[tid] = (pi >= 0) ? d_Hh + po : 0;
                    s_hx_l[tid] = (pi >= 0) ? d_Hl + po : 0;
                    if (leaf_mask[node]) {
                        size_t no = (size_t)node * HID;
                        s_hc_h[tid] = d_LHh + no; s_hc_l[tid] = d_LHl + no;
                    } else {
                        size_t co = (size_t)child_idx[node] * HID;
                        s_hc_h[tid] = d_Hh + co; s_hc_l[tid] = d_Hl + co;
                    }
                } else { s_hx_h[tid] = 0; s_hx_l[tid] = 0; s_hc_h[tid] = 0; s_hc_l[tid] = 0; }
            }
            __syncthreads();

            float acc[16][4];
            #pragma unroll
            for (int i = 0; i < 16; i++)
                #pragma unroll
                for (int c = 0; c < 4; c++) acc[i][c] = 0.f;

            int srow = tid >> 1, skq = (tid & 1) * 64;
            int smc = srow >> 4, srm = srow & 15;
            int sregb = (srm >= 8) ? 1 : 0;
            int sL = (srm & 7) * 4;

            for (int ch = chbeg; ch < 12; ch++) {
                __syncthreads();   // A smem reuse guard
                if (srow < mrows) {
                    bool uhx = (ch < 6);
                    int ko = ch * 128 + skq - (uhx ? 0 : 768);
                    const __nv_bfloat16* ph = uhx ? s_hx_h[srow] : s_hc_h[srow];
                    const __nv_bfloat16* pl = uhx ? s_hx_l[srow] : s_hc_l[srow];
                    #pragma unroll
                    for (int g = 0; g < 8; g++) {
                        int k0 = skq + g * 8;
                        int kc8 = k0 >> 4;
                        int reg = sregb + (((k0 & 15) >> 3) << 1);
                        uint4 vh = ph ? *(const uint4*)(ph + ko + g*8)
                                      : make_uint4(0,0,0,0);
                        uint4 vl = pl ? *(const uint4*)(pl + ko + g*8)
                                      : make_uint4(0,0,0,0);
                        *(uint4*)&A32[(((kc8*8 + smc)*2 + 0)*4 + reg)*32 + sL] = vh;
                        *(uint4*)&A32[(((kc8*8 + smc)*2 + 1)*4 + reg)*32 + sL] = vl;
                    }
                }
                __syncthreads();

                #pragma unroll 1
                for (int kc8 = 0; kc8 < 8; kc8++) {
                    int kcg = ch * 8 + kc8;
                    unsigned ah[4], al[4];
                    #pragma unroll
                    for (int r = 0; r < 4; r++) {
                        ah[r] = A32[(((kc8*8 + mc)*2 + 0)*4 + r)*32 + lane];
                        al[r] = A32[(((kc8*8 + mc)*2 + 1)*4 + r)*32 + lane];
                    }
                    const unsigned long long* Bh = (const unsigned long long*)d_Bfh;
                    const unsigned long long* Bl = (const unsigned long long*)d_Bfl;
                    size_t bbase = (((size_t)jt*96 + kcg)*16)*32 + lane;
                    #pragma unroll
                    for (int i = 0; i < 16; i++) {
                        if (i < nf_cnt) {
                            int nf = nf0 + i;
                            unsigned long long vh = Bh[bbase + (size_t)nf*32];
                            unsigned long long vl = Bl[bbase + (size_t)nf*32];
                            unsigned bh0 = (unsigned)vh, bh1 = (unsigned)(vh >> 32);
                            unsigned bl0 = (unsigned)vl, bl1 = (unsigned)(vl >> 32);
                            mma_bf16(acc[i], ah, bh0, bh1);
                            mma_bf16(acc[i], ah, bl0, bl1);
                            mma_bf16(acc[i], al, bh0, bh1);
                        }
                    }
                }
            }

            // epilogue: write D fragments to d_G
            int erow = mc*16 + (lane >> 2);
            int ecb = (lane & 3) * 2;
            #pragma unroll
            for (int i = 0; i < 16; i++) {
                if (i < nf_cnt) {
                    int col = jt*128 + (nf0 + i)*8 + ecb;
                    if (erow < rows_t)
                        *(float2*)&d_G[(size_t)(r0 + erow)*GC + col]
                            = make_float2(acc[i][0], acc[i][1]);
                    if (erow + 8 < rows_t)
                        *(float2*)&d_G[(size_t)(r0 + erow + 8)*GC + col]
                            = make_float2(acc[i][2], acc[i][3]);
                }
            }
        }

        gbar();

        // gate phase: one warp per row; writes fp32 H + bf16 split
        int gwid = bid * (PTHR/32) + wid;
        int nwarp = GRID * (PTHR/32);
        for (int r = gwid; r < rows; r += nwarp) {
            int node = (r < nb) ? d_listB[w*MAXW + r] : d_listC[w*MAXW + (r - nb)];
            int pi = prev_idx[node];
            const float* cxp = (pi >= 0) ? d_C + (size_t)pi*HID : 0;
            const float* ccp = leaf_mask[node] ? d_LC + (size_t)node*HID
                                               : d_C + (size_t)child_idx[node]*HID;
            const float* gr = d_G + (size_t)r*GC;
            for (int j = lane; j < HID; j += 32) {
                float gi = gr[j] + d_bsc[j];
                float go = gr[HID + j] + d_bsc[HID + j];
                float gf = gr[2*HID + j] + d_bsc[2*HID + j];
                float cx = cxp ? cxp[j] : 0.f;
                float cc = ccp[j];
                float si = 1.f/(1.f + expf(-gi));
                float so = 1.f/(1.f + expf(-go));
                float sf = 1.f/(1.f + expf(-gf));
                float cell = sf*cx + si*cc;
                float hv = so * tanhf(cell);
                size_t idx = (size_t)node*HID + j;
                d_C[idx] = cell;
                d_H[idx] = hv;
                __nv_bfloat16 hh = __float2bfloat16(hv);
                d_Hh[idx] = hh;
                d_Hl[idx] = __float2bfloat16(hv - __bfloat162float(hh));
            }
            __syncwarp();
            if (lane == 0) {
                int ns = d_nextsib[node];
                if (ns >= 0 && atomicSub(&d_deps[ns], 1) == 1) {
                    int s = atomicAdd(&d_nb[w+1], 1);
                    if (s < MAXW) d_listB[(w+1)*MAXW + s] = ns;
                }
                int pp = d_parlast[node];
                if (pp >= 0 && atomicSub(&d_deps[pp], 1) == 1) {
                    if (prev_idx[pp] >= 0) {
                        int s = atomicAdd(&d_nb[w+1], 1);
                        if (s < MAXW) d_listB[(w+1)*MAXW + s] = pp;
                    } else {
                        int s = atomicAdd(&d_nc[w+1], 1);
                        if (s < MAXW) d_listC[(w+1)*MAXW + s] = pp;
                    }
                }
            }
        }
    }
}

// ---------------- launch ----------------
extern "C" void kernel_launch(void* const* d_in, const int* in_sizes, int n_in,
                              void* d_out, int out_size) {
    const int* leaf_mask = (const int*)d_in[0];
    const int* word      = (const int*)d_in[1];
    const int* child_idx = (const int*)d_in[2];
    const int* prev_idx  = (const int*)d_in[3];
    const float* emb = (const float*)d_in[4];
    const float* Wx  = (const float*)d_in[5];
    const float* bx  = (const float*)d_in[6];
    // d_in[7] = Wh unused (encode_h(0) contributes only bh)
    const float* bh  = (const float*)d_in[8];
    const float* Ws  = (const float*)d_in[9];
    const float* bs  = (const float*)d_in[10];
    const float* Wc  = (const float*)d_in[11];
    const float* bc  = (const float*)d_in[12];

    cudaFuncSetAttribute(persist_kernel, cudaFuncAttributeMaxDynamicSharedMemorySize, SMEM_P);

    prep1<<<1024, 256>>>(Ws, Wc, bs, bc);
    prep2<<<(NNODE + 255)/256, 256>>>(leaf_mask, child_idx, prev_idx);
    leaf_kernel<<<dim3((NNODE + LBM - 1)/LBM, 12), LTHR>>>(word, emb, Wx, bx, bh);
    persist_kernel<<<GRID, PTHR, SMEM_P>>>(leaf_mask, child_idx, prev_idx);
    copyout_kernel<<<3, 256>>>((float*)d_out, out_size);
}